// round 12
// baseline (speedup 1.0000x reference)
#include <cuda_runtime.h>
#include <cuda_fp16.h>
#include <cstdint>
#include <cstddef>

// m16n8k16 row.col f32.f16.f16.f32 (family-common PTX, works on plain sm_103)
#define MMA_F16(c, a, b0, b1)                                                   \
    asm volatile("mma.sync.aligned.m16n8k16.row.col.f32.f16.f16.f32 "           \
                 "{%0,%1,%2,%3},{%4,%5,%6,%7},{%8,%9},{%0,%1,%2,%3};"           \
                 : "+f"((c)[0]), "+f"((c)[1]), "+f"((c)[2]), "+f"((c)[3])       \
                 : "r"((a)[0]), "r"((a)[1]), "r"((a)[2]), "r"((a)[3]),          \
                   "r"(b0), "r"(b1))

// ---------------- problem constants ----------------
static constexpr int BATCH = 16;
static constexpr int C     = 64;     // CIN == COUT
static constexpr int HW    = 112;
static constexpr int TH    = 8;      // tile h  -> M = 128 pixels per CTA
static constexpr int TW    = 16;     // tile w

// halo layout (32-bit words): [s(4)][row(10)][t(4)][w(18)*2 + pad4]
//   word(c, r, w): s=c>>4, pl=(c&15)>>1, t=pl&3, hi=pl>>2, half=c&1
//   addr = s*1600 + r*160 + t*40 + w*2 + hi
//   LDS.64 at (t, w) returns pairs {t, t+4} = both K-halves of one A column.
//   Bank check (16-lane phase): t*40+w*2 mod 32 = t*8+g*2 -> 16 distinct evens,
//   64-bit pair covers odds -> conflict-free.
static constexpr int T_STR = 40;     // per-t stride (words)
static constexpr int R_STR = 160;    // per-row stride
static constexpr int S_STR = 1600;   // per-s stride

// fragment-ordered fp16 weights: 288 chunks x 512 B = 73728 B
__device__ uint32_t g_B2[36864];

// ---- prep kernel: wt[fp32, (cin*9+kpos) x 64] -> fragment-ordered fp16 pairs ----
__global__ void __launch_bounds__(256, 1)
prep_weights(const float* __restrict__ wt)
{
    int idx    = blockIdx.x * 256 + threadIdx.x;   // 0..36863
    int chunk  = idx >> 7;
    int within = idx & 127;
    int lane = within >> 2, r = within & 3;
    int h2   = chunk & 1;
    int wn   = (chunk >> 1) & 1;
    int s    = (chunk >> 2) & 3;
    int kpos = chunk >> 4;                          // 0..8
    int nt   = h2 * 2 + (r >> 1);
    int breg = r & 1;
    int g = lane >> 2, t = lane & 3;
    int co  = wn * 32 + nt * 8 + g;
    int cin = s * 16 + 2 * t + breg * 8;
    __half lo = __float2half_rn(wt[((size_t)cin * 9 + kpos) * 64 + co]);
    __half hi = __float2half_rn(wt[((size_t)(cin + 1) * 9 + kpos) * 64 + co]);
    __half2 v = __halves2half2(lo, hi);
    g_B2[idx] = *(uint32_t*)&v;
}

__global__ void __launch_bounds__(256, 3)
conv3x3_f16_mma(const float* __restrict__ x,
                const float* __restrict__ bias,
                float* __restrict__ out)
{
    __shared__ uint32_t halo32[4 * S_STR];          // 6400 words = 25600 B

    const int tid  = threadIdx.x;
    const int lane = tid & 31;
    const int wid  = tid >> 5;
    const int wm   = wid >> 1;          // 0..3 : 2 h-rows each
    const int wn   = wid & 1;           // 0..1 : 32 couts each
    const int g    = lane >> 2;         // groupID 0..7
    const int t    = lane & 3;          // thread-in-group

    const int w0 = blockIdx.x * TW;
    const int h0 = blockIdx.y * TH;
    const int b  = blockIdx.z;

    // ---- halo load: channel-PAIR per element: 2 LDG + 1 cvt.f16x2 + 1 STS.32 ----
    // pair-space: 32 pairs x 10 rows x 18 cols = 5760 = 22.5 * 256
    #pragma unroll 4
    for (int i = 0; i < 23; ++i) {
        int idx = tid + i * 256;
        if (idx < 5760) {
            int p   = idx / 180;            // channel pair 0..31
            int rem = idx - p * 180;
            int r   = rem / 18;
            int w   = rem - r * 18;
            int gh = h0 - 1 + r, gw = w0 - 1 + w;
            float v0 = 0.f, v1 = 0.f;
            if ((unsigned)gh < (unsigned)HW && (unsigned)gw < (unsigned)HW) {
                const float* src = x + (((size_t)b * C + 2 * p) * HW + gh) * HW + gw;
                v0 = __ldg(src);
                v1 = __ldg(src + (size_t)HW * HW);
            }
            uint32_t pk;    // {lo = v0 (even c), hi = v1 (odd c)}
            asm("cvt.rn.f16x2.f32 %0, %1, %2;" : "=r"(pk) : "f"(v1), "f"(v0));
            int s  = p >> 3;
            int pl = p & 7;
            halo32[s * S_STR + r * R_STR + (pl & 3) * T_STR + w * 2 + (pl >> 2)] = pk;
        }
    }
    __syncthreads();

    float acc[2][4][4];                 // [mt][nt][creg]
    #pragma unroll
    for (int i = 0; i < 2; ++i)
        #pragma unroll
        for (int j = 0; j < 4; ++j)
            #pragma unroll
            for (int k = 0; k < 4; ++k) acc[i][j][k] = 0.f;

    const uint4* bq = (const uint4*)g_B2 + wn * 64 + lane;
    const uint32_t* aw = halo32 + (wm * 2) * R_STR + t * T_STR + g * 2;

    // loop order: s (outer, rolled) -> kw -> kh; A rows factored across kh:
    // 4 row-fragments per (s,kw), each one LDS.64 per w-column.
    #pragma unroll 1
    for (int s = 0; s < 4; ++s) {
        const uint32_t* as  = aw + s * S_STR;
        const uint4*    bqs = bq + s * 128;

        #pragma unroll
        for (int kw = 0; kw < 3; ++kw) {
            const uint32_t* p = as + kw * 2;
            // A[d]: halo row wm*2+d; LDS.64 -> {pair t, pair t+4} per w-column
            uint32_t A[4][4];
            #pragma unroll
            for (int d = 0; d < 4; ++d) {
                uint2 u = *(const uint2*)(p + d * R_STR);        // w = g+kw : {a0,a2}
                uint2 v = *(const uint2*)(p + d * R_STR + 16);   // w = g+8+kw : {a1,a3}
                A[d][0] = u.x; A[d][1] = v.x; A[d][2] = u.y; A[d][3] = v.y;
            }
            #pragma unroll
            for (int kh = 0; kh < 3; ++kh) {
                const int kpos = kh * 3 + kw;
                uint32_t Bf[8];
                *(uint4*)&Bf[0] = __ldg(bqs + kpos * 512);        // h2=0: nt0,nt1
                *(uint4*)&Bf[4] = __ldg(bqs + kpos * 512 + 32);   // h2=1: nt2,nt3

                #pragma unroll
                for (int mt = 0; mt < 2; ++mt)
                    #pragma unroll
                    for (int nt = 0; nt < 4; ++nt)
                        MMA_F16(acc[mt][nt], A[mt + kh], Bf[2 * nt], Bf[2 * nt + 1]);
            }
        }
    }

    // ---- epilogue ----
    #pragma unroll
    for (int nt = 0; nt < 4; ++nt) {
        const int co0 = wn * 32 + nt * 8 + 2 * t;
        const float bz0 = __ldg(bias + co0);
        const float bz1 = __ldg(bias + co0 + 1);
        #pragma unroll
        for (int mt = 0; mt < 2; ++mt) {
            const int h = h0 + wm * 2 + mt;
            float* p0 = out + (((size_t)b * C + co0) * HW + h) * HW + w0;
            float* p1 = p0 + (size_t)HW * HW;
            p0[g]     = acc[mt][nt][0] + bz0;   // w=g,   cout co0
            p1[g]     = acc[mt][nt][1] + bz1;   // w=g,   cout co0+1
            p0[g + 8] = acc[mt][nt][2] + bz0;   // w=g+8, cout co0
            p1[g + 8] = acc[mt][nt][3] + bz1;   // w=g+8, cout co0+1
        }
    }
}

extern "C" void kernel_launch(void* const* d_in, const int* in_sizes, int n_in,
                              void* d_out, int out_size)
{
    const float* x    = (const float*)d_in[0];
    const float* wt   = (const float*)d_in[1];
    const float* bias = (const float*)d_in[2];
    float* out = (float*)d_out;

    prep_weights<<<144, 256>>>(wt);     // 144*256 == 36864 exactly

    dim3 grid(HW / TW, HW / TH, BATCH);   // 7 x 14 x 16
    conv3x3_f16_mma<<<grid, 256>>>(x, bias, out);
}

// round 13
// speedup vs baseline: 1.0263x; 1.0263x over previous
#include <cuda_runtime.h>
#include <cuda_fp16.h>
#include <cstdint>
#include <cstddef>

// m16n8k16 row.col f32.f16.f16.f32 (family-common PTX, works on plain sm_103)
#define MMA_F16(c, a, b0, b1)                                                   \
    asm volatile("mma.sync.aligned.m16n8k16.row.col.f32.f16.f16.f32 "           \
                 "{%0,%1,%2,%3},{%4,%5,%6,%7},{%8,%9},{%0,%1,%2,%3};"           \
                 : "+f"((c)[0]), "+f"((c)[1]), "+f"((c)[2]), "+f"((c)[3])       \
                 : "r"((a)[0]), "r"((a)[1]), "r"((a)[2]), "r"((a)[3]),          \
                   "r"(b0), "r"(b1))

// ---------------- problem constants ----------------
static constexpr int BATCH = 16;
static constexpr int C     = 64;     // CIN == COUT
static constexpr int HW    = 112;
static constexpr int TH    = 8;      // tile h  -> M = 128 pixels per CTA
static constexpr int TW    = 16;     // tile w

// halo: 32 channel-pairs x 10 rows x 18 cols of half2 words
static constexpr int PRS   = 20;     // row stride in words (half2)
static constexpr int PPL   = 200;    // pair-plane stride in words; 200 % 32 == 8 -> conflict-free

// fragment-ordered fp16 weights: 288 chunks x 512 B = 73728 B
__device__ uint32_t g_B2[36864];

// ---- prep kernel: wt[fp32, (cin*9+kpos) x 64] -> fragment-ordered fp16 pairs ----
__global__ void __launch_bounds__(256, 1)
prep_weights(const float* __restrict__ wt)
{
    int idx    = blockIdx.x * 256 + threadIdx.x;   // 0..36863
    int chunk  = idx >> 7;
    int within = idx & 127;
    int lane = within >> 2, r = within & 3;
    int h2   = chunk & 1;
    int wn   = (chunk >> 1) & 1;
    int s    = (chunk >> 2) & 3;
    int kpos = chunk >> 4;                          // 0..8
    int nt   = h2 * 2 + (r >> 1);
    int breg = r & 1;
    int g = lane >> 2, t = lane & 3;
    int co  = wn * 32 + nt * 8 + g;
    int cin = s * 16 + 2 * t + breg * 8;
    __half lo = __float2half_rn(wt[((size_t)cin * 9 + kpos) * 64 + co]);
    __half hi = __float2half_rn(wt[((size_t)(cin + 1) * 9 + kpos) * 64 + co]);
    __half2 v = __halves2half2(lo, hi);
    g_B2[idx] = *(uint32_t*)&v;
}

__global__ void __launch_bounds__(256, 3)
conv3x3_f16_mma(const float* __restrict__ x,
                const float* __restrict__ bias,
                float* __restrict__ out)
{
    __shared__ uint32_t halo32[32 * PPL];           // 6400 words = 25600 B

    const int tid  = threadIdx.x;
    const int lane = tid & 31;
    const int wid  = tid >> 5;
    const int wm   = wid >> 1;          // 0..3 : 2 h-rows each
    const int wn   = wid & 1;           // 0..1 : 32 couts each
    const int g    = lane >> 2;         // groupID 0..7
    const int t    = lane & 3;          // thread-in-group

    const int w0 = blockIdx.x * TW;
    const int h0 = blockIdx.y * TH;
    const int b  = blockIdx.z;

    // ---- halo load: one channel-PAIR element per thread-step:
    //      2 coalesced LDG.32 + 1 cvt.rn.f16x2 + 1 STS.32 into word
    //      halo32[p*PPL + r*PRS + w]  (identical layout to the 70.9us kernel)
    #pragma unroll 4
    for (int i = 0; i < 23; ++i) {      // 23*256 >= 5760 = 32 pairs *10*18
        int idx = tid + i * 256;
        if (i < 22 || idx < 5760) {
            int p   = idx / 180;            // channel pair 0..31
            int rem = idx - p * 180;
            int r   = rem / 18;
            int w   = rem - r * 18;
            int gh = h0 - 1 + r, gw = w0 - 1 + w;
            float v0 = 0.f, v1 = 0.f;
            if ((unsigned)gh < (unsigned)HW && (unsigned)gw < (unsigned)HW) {
                const float* src = x + (((size_t)b * C + 2 * p) * HW + gh) * HW + gw;
                v0 = __ldg(src);
                v1 = __ldg(src + (size_t)HW * HW);
            }
            uint32_t pk;    // {lo = even channel, hi = odd channel}
            asm("cvt.rn.f16x2.f32 %0, %1, %2;" : "=r"(pk) : "f"(v1), "f"(v0));
            halo32[p * PPL + r * PRS + w] = pk;
        }
    }
    __syncthreads();

    float acc[2][4][4];                 // [mt][nt][creg]
    #pragma unroll
    for (int i = 0; i < 2; ++i)
        #pragma unroll
        for (int j = 0; j < 4; ++j)
            #pragma unroll
            for (int k = 0; k < 4; ++k) acc[i][j][k] = 0.f;

    const uint4* bq = (const uint4*)g_B2 + wn * 64 + lane;

    // loop order: s (outer, rolled) -> kw -> kh; A rows (wm*2 + mt + kh) factored:
    // only 4 row-fragments A[0..3] per (s,kw), reused by acc[mt] += A[mt+kh] * B[kh]
    #pragma unroll 1
    for (int s = 0; s < 4; ++s) {
        const uint32_t* aw = halo32 + t * PPL + (wm * 2) * PRS + g + s * 8 * PPL;
        const uint4*    bqs = bq + s * 128;

        #pragma unroll
        for (int kw = 0; kw < 3; ++kw) {
            const uint32_t* p = aw + kw;
            // A[d]: halo row wm*2 + d (d = mt + kh), both w-halves, both K-half pairs
            uint32_t A[4][4];
            #pragma unroll
            for (int d = 0; d < 4; ++d) {
                A[d][0] = p[d * PRS];                // pair t,   w=g
                A[d][1] = p[d * PRS + 8];            // pair t,   w=g+8
                A[d][2] = p[d * PRS + 4 * PPL];      // pair t+4, w=g
                A[d][3] = p[d * PRS + 4 * PPL + 8];  // pair t+4, w=g+8
            }
            #pragma unroll
            for (int kh = 0; kh < 3; ++kh) {
                const int kpos = kh * 3 + kw;
                uint32_t Bf[8];
                *(uint4*)&Bf[0] = __ldg(bqs + kpos * 512);        // h2=0: nt0,nt1
                *(uint4*)&Bf[4] = __ldg(bqs + kpos * 512 + 32);   // h2=1: nt2,nt3

                #pragma unroll
                for (int mt = 0; mt < 2; ++mt)
                    #pragma unroll
                    for (int nt = 0; nt < 4; ++nt)
                        MMA_F16(acc[mt][nt], A[mt + kh], Bf[2 * nt], Bf[2 * nt + 1]);
            }
        }
    }

    // ---- epilogue ----
    #pragma unroll
    for (int nt = 0; nt < 4; ++nt) {
        const int co0 = wn * 32 + nt * 8 + 2 * t;
        const float bz0 = __ldg(bias + co0);
        const float bz1 = __ldg(bias + co0 + 1);
        #pragma unroll
        for (int mt = 0; mt < 2; ++mt) {
            const int h = h0 + wm * 2 + mt;
            float* p0 = out + (((size_t)b * C + co0) * HW + h) * HW + w0;
            float* p1 = p0 + (size_t)HW * HW;
            p0[g]     = acc[mt][nt][0] + bz0;   // w=g,   cout co0
            p1[g]     = acc[mt][nt][1] + bz1;   // w=g,   cout co0+1
            p0[g + 8] = acc[mt][nt][2] + bz0;   // w=g+8, cout co0
            p1[g + 8] = acc[mt][nt][3] + bz1;   // w=g+8, cout co0+1
        }
    }
}

extern "C" void kernel_launch(void* const* d_in, const int* in_sizes, int n_in,
                              void* d_out, int out_size)
{
    const float* x    = (const float*)d_in[0];
    const float* wt   = (const float*)d_in[1];
    const float* bias = (const float*)d_in[2];
    float* out = (float*)d_out;

    prep_weights<<<144, 256>>>(wt);     // 144*256 == 36864 exactly

    dim3 grid(HW / TW, HW / TH, BATCH);   // 7 x 14 x 16
    conv3x3_f16_mma<<<grid, 256>>>(x, bias, out);
}

// round 14
// speedup vs baseline: 1.1455x; 1.1161x over previous
#include <cuda_runtime.h>
#include <cuda_fp16.h>
#include <cstdint>
#include <cstddef>

// m16n8k16 row.col f32.f16.f16.f32 (family-common PTX, works on plain sm_103)
#define MMA_F16(c, a, b0, b1)                                                   \
    asm volatile("mma.sync.aligned.m16n8k16.row.col.f32.f16.f16.f32 "           \
                 "{%0,%1,%2,%3},{%4,%5,%6,%7},{%8,%9},{%0,%1,%2,%3};"           \
                 : "+f"((c)[0]), "+f"((c)[1]), "+f"((c)[2]), "+f"((c)[3])       \
                 : "r"((a)[0]), "r"((a)[1]), "r"((a)[2]), "r"((a)[3]),          \
                   "r"(b0), "r"(b1))

// ---------------- problem constants ----------------
static constexpr int BATCH = 16;
static constexpr int C     = 64;     // CIN == COUT
static constexpr int HW    = 112;
static constexpr int TH    = 8;      // tile h  -> M = 128 pixels per CTA
static constexpr int TW    = 16;     // tile w

// halo: 32 channel-pairs x 10 rows x 18 cols of half2 words
static constexpr int PRS   = 20;     // row stride in words (half2)
static constexpr int PPL   = 200;    // pair-plane stride in words; 200 % 32 == 8 -> conflict-free

// fragment-ordered fp16 weights: 288 chunks x 512 B = 73728 B
__device__ uint32_t g_B2[36864];

// ---- prep kernel: wt[fp32, (cin*9+kpos) x 64] -> fragment-ordered fp16 pairs ----
__global__ void __launch_bounds__(256, 1)
prep_weights(const float* __restrict__ wt)
{
    int idx    = blockIdx.x * 256 + threadIdx.x;   // 0..36863
    int chunk  = idx >> 7;
    int within = idx & 127;
    int lane = within >> 2, r = within & 3;
    int h2   = chunk & 1;
    int wn   = (chunk >> 1) & 1;
    int s    = (chunk >> 2) & 3;
    int kpos = chunk >> 4;                          // 0..8
    int nt   = h2 * 2 + (r >> 1);
    int breg = r & 1;
    int g = lane >> 2, t = lane & 3;
    int co  = wn * 32 + nt * 8 + g;
    int cin = s * 16 + 2 * t + breg * 8;
    __half lo = __float2half_rn(wt[((size_t)cin * 9 + kpos) * 64 + co]);
    __half hi = __float2half_rn(wt[((size_t)(cin + 1) * 9 + kpos) * 64 + co]);
    __half2 v = __halves2half2(lo, hi);
    g_B2[idx] = *(uint32_t*)&v;
}

__global__ void __launch_bounds__(256, 3)
conv3x3_f16_mma(const float* __restrict__ x,
                const float* __restrict__ bias,
                float* __restrict__ out)
{
    __shared__ uint32_t halo32[32 * PPL];           // 6400 words = 25600 B
    __half* haloh = (__half*)halo32;

    const int tid  = threadIdx.x;
    const int lane = tid & 31;
    const int wid  = tid >> 5;
    const int wm   = wid >> 1;          // 0..3 : 2 h-rows each
    const int wn   = wid & 1;           // 0..1 : 32 couts each
    const int g    = lane >> 2;         // groupID 0..7
    const int t    = lane & 3;          // thread-in-group

    const int w0 = blockIdx.x * TW;
    const int h0 = blockIdx.y * TH;
    const int b  = blockIdx.z;

    // ---- halo load: 64 cin x 10 x 18 -> fp16 channel-pair layout, zero padded ----
    #pragma unroll 5
    for (int i = 0; i < 45; ++i) {      // 45*256 == 64*10*18 exactly
        int idx = tid + i * 256;
        int c   = idx / 180;
        int rem = idx - c * 180;
        int r   = rem / 18;
        int w   = rem - r * 18;
        int gh = h0 - 1 + r, gw = w0 - 1 + w;
        float v = 0.f;
        if ((unsigned)gh < (unsigned)HW && (unsigned)gw < (unsigned)HW)
            v = x[(((size_t)b * C + c) * HW + gh) * HW + gw];
        haloh[(c >> 1) * (2 * PPL) + r * (2 * PRS) + 2 * w + (c & 1)] = __float2half_rn(v);
    }
    __syncthreads();

    float acc[2][4][4];                 // [mt][nt][creg]
    #pragma unroll
    for (int i = 0; i < 2; ++i)
        #pragma unroll
        for (int j = 0; j < 4; ++j)
            #pragma unroll
            for (int k = 0; k < 4; ++k) acc[i][j][k] = 0.f;

    const uint4* bq = (const uint4*)g_B2 + wn * 64 + lane;
    const uint32_t* awb = halo32 + t * PPL + (wm * 2) * PRS + g;

    // FULLY UNROLLED: s -> kw -> kh. All LDS/LDG addresses become base+immediate;
    // ptxas gets a 36-step barrier-free window to pipeline loads ahead of MMAs.
    #pragma unroll
    for (int s = 0; s < 4; ++s) {
        #pragma unroll
        for (int kw = 0; kw < 3; ++kw) {
            const uint32_t* p = awb + s * 8 * PPL + kw;
            // A[d]: halo row wm*2 + d (d = mt + kh), both w-halves, both K-half pairs
            uint32_t A[4][4];
            #pragma unroll
            for (int d = 0; d < 4; ++d) {
                A[d][0] = p[d * PRS];                // pair t,   w=g
                A[d][1] = p[d * PRS + 8];            // pair t,   w=g+8
                A[d][2] = p[d * PRS + 4 * PPL];      // pair t+4, w=g
                A[d][3] = p[d * PRS + 4 * PPL + 8];  // pair t+4, w=g+8
            }
            #pragma unroll
            for (int kh = 0; kh < 3; ++kh) {
                const int kpos = kh * 3 + kw;
                uint32_t Bf[8];
                *(uint4*)&Bf[0] = __ldg(bq + s * 128 + kpos * 512);        // h2=0
                *(uint4*)&Bf[4] = __ldg(bq + s * 128 + kpos * 512 + 32);   // h2=1

                #pragma unroll
                for (int mt = 0; mt < 2; ++mt)
                    #pragma unroll
                    for (int nt = 0; nt < 4; ++nt)
                        MMA_F16(acc[mt][nt], A[mt + kh], Bf[2 * nt], Bf[2 * nt + 1]);
            }
        }
    }

    // ---- epilogue ----
    #pragma unroll
    for (int nt = 0; nt < 4; ++nt) {
        const int co0 = wn * 32 + nt * 8 + 2 * t;
        const float bz0 = __ldg(bias + co0);
        const float bz1 = __ldg(bias + co0 + 1);
        #pragma unroll
        for (int mt = 0; mt < 2; ++mt) {
            const int h = h0 + wm * 2 + mt;
            float* p0 = out + (((size_t)b * C + co0) * HW + h) * HW + w0;
            float* p1 = p0 + (size_t)HW * HW;
            p0[g]     = acc[mt][nt][0] + bz0;   // w=g,   cout co0
            p1[g]     = acc[mt][nt][1] + bz1;   // w=g,   cout co0+1
            p0[g + 8] = acc[mt][nt][2] + bz0;   // w=g+8, cout co0
            p1[g + 8] = acc[mt][nt][3] + bz1;   // w=g+8, cout co0+1
        }
    }
}

extern "C" void kernel_launch(void* const* d_in, const int* in_sizes, int n_in,
                              void* d_out, int out_size)
{
    const float* x    = (const float*)d_in[0];
    const float* wt   = (const float*)d_in[1];
    const float* bias = (const float*)d_in[2];
    float* out = (float*)d_out;

    prep_weights<<<144, 256>>>(wt);     // 144*256 == 36864 exactly

    dim3 grid(HW / TW, HW / TH, BATCH);   // 7 x 14 x 16
    conv3x3_f16_mma<<<grid, 256>>>(x, bias, out);
}

// round 16
// speedup vs baseline: 1.1547x; 1.0080x over previous
#include <cuda_runtime.h>
#include <cuda_fp16.h>
#include <cstdint>
#include <cstddef>

// m16n8k16 row.col f32.f16.f16.f32 (family-common PTX, works on plain sm_103)
#define MMA_F16(c, a, b0, b1)                                                   \
    asm volatile("mma.sync.aligned.m16n8k16.row.col.f32.f16.f16.f32 "           \
                 "{%0,%1,%2,%3},{%4,%5,%6,%7},{%8,%9},{%0,%1,%2,%3};"           \
                 : "+f"((c)[0]), "+f"((c)[1]), "+f"((c)[2]), "+f"((c)[3])       \
                 : "r"((a)[0]), "r"((a)[1]), "r"((a)[2]), "r"((a)[3]),          \
                   "r"(b0), "r"(b1))

// ---------------- problem constants ----------------
static constexpr int BATCH = 16;
static constexpr int C     = 64;     // CIN == COUT
static constexpr int HW    = 112;
static constexpr int TH    = 8;      // tile h  -> M = 128 pixels per CTA
static constexpr int TW    = 16;     // tile w

// halo: 32 channel-pairs x 10 rows x 18 cols of half2 words
static constexpr int PRS   = 20;     // row stride in words (half2)
static constexpr int PPL   = 200;    // pair-plane stride in words; 200 % 32 == 8 -> conflict-free

// fragment-ordered fp16 weights: 288 chunks x 512 B = 73728 B
__device__ uint32_t g_B2[36864];

// ---- prep kernel: wt[fp32, (cin*9+kpos) x 64] -> fragment-ordered fp16 pairs ----
__global__ void __launch_bounds__(256, 1)
prep_weights(const float* __restrict__ wt)
{
    int idx    = blockIdx.x * 256 + threadIdx.x;   // 0..36863
    int chunk  = idx >> 7;
    int within = idx & 127;
    int lane = within >> 2, r = within & 3;
    int h2   = chunk & 1;
    int wn   = (chunk >> 1) & 1;
    int s    = (chunk >> 2) & 3;
    int kpos = chunk >> 4;                          // 0..8
    int nt   = h2 * 2 + (r >> 1);
    int breg = r & 1;
    int g = lane >> 2, t = lane & 3;
    int co  = wn * 32 + nt * 8 + g;
    int cin = s * 16 + 2 * t + breg * 8;
    __half lo = __float2half_rn(wt[((size_t)cin * 9 + kpos) * 64 + co]);
    __half hi = __float2half_rn(wt[((size_t)(cin + 1) * 9 + kpos) * 64 + co]);
    __half2 v = __halves2half2(lo, hi);
    g_B2[idx] = *(uint32_t*)&v;
}

__global__ void __launch_bounds__(256, 4)
conv3x3_f16_mma(const float* __restrict__ x,
                const float* __restrict__ bias,
                float* __restrict__ out)
{
    __shared__ uint32_t halo32[32 * PPL];           // 6400 words = 25600 B
    __half* haloh = (__half*)halo32;

    const int tid  = threadIdx.x;
    const int lane = tid & 31;
    const int wid  = tid >> 5;
    const int wm   = wid >> 1;          // 0..3 : 2 h-rows each
    const int wn   = wid & 1;           // 0..1 : 32 couts each
    const int g    = lane >> 2;         // groupID 0..7
    const int t    = lane & 3;          // thread-in-group

    const int w0 = blockIdx.x * TW;
    const int h0 = blockIdx.y * TH;
    const int b  = blockIdx.z;

    // ---- halo load: 64 cin x 10 x 18 -> fp16 channel-pair layout, zero padded ----
    #pragma unroll 5
    for (int i = 0; i < 45; ++i) {      // 45*256 == 64*10*18 exactly
        int idx = tid + i * 256;
        int c   = idx / 180;
        int rem = idx - c * 180;
        int r   = rem / 18;
        int w   = rem - r * 18;
        int gh = h0 - 1 + r, gw = w0 - 1 + w;
        float v = 0.f;
        if ((unsigned)gh < (unsigned)HW && (unsigned)gw < (unsigned)HW)
            v = x[(((size_t)b * C + c) * HW + gh) * HW + gw];
        haloh[(c >> 1) * (2 * PPL) + r * (2 * PRS) + 2 * w + (c & 1)] = __float2half_rn(v);
    }
    __syncthreads();

    float acc[2][4][4];                 // [mt][nt][creg]
    #pragma unroll
    for (int i = 0; i < 2; ++i)
        #pragma unroll
        for (int j = 0; j < 4; ++j)
            #pragma unroll
            for (int k = 0; k < 4; ++k) acc[i][j][k] = 0.f;

    const uint4* bq = (const uint4*)g_B2 + wn * 64 + lane;
    const uint32_t* awb = halo32 + t * PPL + (wm * 2) * PRS + g;

    // FULLY UNROLLED: s -> kw -> kh. All LDS/LDG addresses become base+immediate;
    // ptxas gets a 36-step barrier-free window to pipeline loads ahead of MMAs.
    #pragma unroll
    for (int s = 0; s < 4; ++s) {
        #pragma unroll
        for (int kw = 0; kw < 3; ++kw) {
            const uint32_t* p = awb + s * 8 * PPL + kw;
            // A[d]: halo row wm*2 + d (d = mt + kh), both w-halves, both K-half pairs
            uint32_t A[4][4];
            #pragma unroll
            for (int d = 0; d < 4; ++d) {
                A[d][0] = p[d * PRS];                // pair t,   w=g
                A[d][1] = p[d * PRS + 8];            // pair t,   w=g+8
                A[d][2] = p[d * PRS + 4 * PPL];      // pair t+4, w=g
                A[d][3] = p[d * PRS + 4 * PPL + 8];  // pair t+4, w=g+8
            }
            #pragma unroll
            for (int kh = 0; kh < 3; ++kh) {
                const int kpos = kh * 3 + kw;
                uint32_t Bf[8];
                *(uint4*)&Bf[0] = __ldg(bq + s * 128 + kpos * 512);        // h2=0
                *(uint4*)&Bf[4] = __ldg(bq + s * 128 + kpos * 512 + 32);   // h2=1

                #pragma unroll
                for (int mt = 0; mt < 2; ++mt)
                    #pragma unroll
                    for (int nt = 0; nt < 4; ++nt)
                        MMA_F16(acc[mt][nt], A[mt + kh], Bf[2 * nt], Bf[2 * nt + 1]);
            }
        }
    }

    // ---- epilogue ----
    #pragma unroll
    for (int nt = 0; nt < 4; ++nt) {
        const int co0 = wn * 32 + nt * 8 + 2 * t;
        const float bz0 = __ldg(bias + co0);
        const float bz1 = __ldg(bias + co0 + 1);
        #pragma unroll
        for (int mt = 0; mt < 2; ++mt) {
            const int h = h0 + wm * 2 + mt;
            float* p0 = out + (((size_t)b * C + co0) * HW + h) * HW + w0;
            float* p1 = p0 + (size_t)HW * HW;
            p0[g]     = acc[mt][nt][0] + bz0;   // w=g,   cout co0
            p1[g]     = acc[mt][nt][1] + bz1;   // w=g,   cout co0+1
            p0[g + 8] = acc[mt][nt][2] + bz0;   // w=g+8, cout co0
            p1[g + 8] = acc[mt][nt][3] + bz1;   // w=g+8, cout co0+1
        }
    }
}

extern "C" void kernel_launch(void* const* d_in, const int* in_sizes, int n_in,
                              void* d_out, int out_size)
{
    const float* x    = (const float*)d_in[0];
    const float* wt   = (const float*)d_in[1];
    const float* bias = (const float*)d_in[2];
    float* out = (float*)d_out;

    prep_weights<<<144, 256>>>(wt);     // 144*256 == 36864 exactly

    dim3 grid(HW / TW, HW / TH, BATCH);   // 7 x 14 x 16
    conv3x3_f16_mma<<<grid, 256>>>(x, bias, out);
}